// round 16
// baseline (speedup 1.0000x reference)
#include <cuda_runtime.h>
#include <cuda_bf16.h>
#include <cuda_fp8.h>
#include <math.h>

#define NND 512
#define SD  32
#define HM  64
#define TI  32    // i-rows per block
#define TJS 4     // j-cols per subtile
#define NSUB 4    // subtiles per block (block covers 16 j total)

// Scratch (device globals: no allocation allowed)
__device__ float g_A[NND * HM];     // row term  (incl. b_i*wbi)
__device__ float g_B[NND * HM];     // col term  (incl. b_j*wbj + mp_b1)
__device__ float g_msg[NND * SD];   // msg_sum
__device__ float g_h0[NND * SD];
__device__ float g_h1[NND * SD];
__device__ float g_W1T[67 * 64];    // W1 transposed: [d][k], coalesced k

__device__ __forceinline__ float frelu(float x) { return fmaxf(x, 0.f); }

__device__ __forceinline__ unsigned packbf(float lo, float hi) {
    __nv_bfloat162 h = __floats2bfloat162_rn(lo, hi);
    return *reinterpret_cast<unsigned*>(&h);
}

// pack 4 floats (k ascending) into one .b32 of e4m3 (LSB = first)
__device__ __forceinline__ unsigned packf8x4(float v0, float v1, float v2, float v3) {
    __nv_fp8x2_storage_t lo = __nv_cvt_float2_to_fp8x2(make_float2(v0, v1),
                                                       __NV_SATFINITE, __NV_E4M3);
    __nv_fp8x2_storage_t hi = __nv_cvt_float2_to_fp8x2(make_float2(v2, v3),
                                                       __NV_SATFINITE, __NV_E4M3);
    return (unsigned)lo | ((unsigned)hi << 16);
}

__device__ __forceinline__ void mma16816(float c[4],
                                         unsigned a0, unsigned a1, unsigned a2, unsigned a3,
                                         unsigned b0, unsigned b1) {
    asm volatile(
        "mma.sync.aligned.m16n8k16.row.col.f32.bf16.bf16.f32 "
        "{%0,%1,%2,%3}, {%4,%5,%6,%7}, {%8,%9}, {%0,%1,%2,%3};"
        : "+f"(c[0]), "+f"(c[1]), "+f"(c[2]), "+f"(c[3])
        : "r"(a0), "r"(a1), "r"(a2), "r"(a3), "r"(b0), "r"(b1));
}

__device__ __forceinline__ void mma16832(float c[4],
                                         unsigned a0, unsigned a1, unsigned a2, unsigned a3,
                                         unsigned b0, unsigned b1) {
    asm volatile(
        "mma.sync.aligned.m16n8k32.row.col.f32.e4m3.e4m3.f32 "
        "{%0,%1,%2,%3}, {%4,%5,%6,%7}, {%8,%9}, {%0,%1,%2,%3};"
        : "+f"(c[0]), "+f"(c[1]), "+f"(c[2]), "+f"(c[3])
        : "r"(a0), "r"(a1), "r"(a2), "r"(a3), "r"(b0), "r"(b1));
}

// ------------------------------------------ step-0: h = 0 closed-form prep + zeroing
__global__ void __launch_bounds__(256) prep0_kernel(
    const float* __restrict__ b,
    const float* __restrict__ mp_W1, const float* __restrict__ mp_b1)
{
    const int idx = blockIdx.x * 256 + threadIdx.x;   // grid 128 -> 32768 = NND*HM
    const int i = idx >> 6, k = idx & 63;
    const float bi = b[i];
    g_A[idx] = bi * mp_W1[k * 67 + 65];
    g_B[idx] = fmaf(bi, mp_W1[k * 67 + 66], mp_b1[k]);
    if (idx < NND * SD) { g_h0[idx] = 0.f; g_msg[idx] = 0.f; }
    if (idx < 64 * 67) {
        const int kk = idx / 67, d = idx % 67;
        g_W1T[d * 64 + kk] = mp_W1[idx];
    }
}

// ------------------------------------------------- per-step rank-term prep (W1T path)
__global__ void __launch_bounds__(256) prep_kernel(
    const float* __restrict__ hin, const float* __restrict__ b,
    const float* __restrict__ mp_b1)
{
    __shared__ float sh[4 * 33];
    __shared__ float sb[4];
    const int t = threadIdx.x;
    const int n0 = blockIdx.x * 4;
    if (t < 128) {
        const int r = t >> 5, c = t & 31;
        sh[r * 33 + c] = hin[(n0 + r) * SD + c];
        g_msg[(n0 + r) * SD + c] = 0.f;
    }
    if (t < 4) sb[t] = b[n0 + t];
    __syncthreads();
    const int k = t & 63, il = t >> 6;
    float a = 0.f, bb = mp_b1[k];
#pragma unroll
    for (int d = 0; d < SD; d++) {
        const float hv = sh[il * 33 + d];
        a  += g_W1T[d * 64 + k] * hv;
        bb += g_W1T[(32 + d) * 64 + k] * hv;
    }
    const float bi = sb[il];
    g_A[(n0 + il) * HM + k] = a + bi * g_W1T[65 * 64 + k];
    g_B[(n0 + il) * HM + k] = bb + bi * g_W1T[66 * 64 + k];
}

// ---------------------------------------------------- pairwise message MLP
// Stage 1 on fp8 e4m3 m16n8k32 (half the MMA count + half the W2-fragment LDS of
// bf16 k16); stage 2 stays proven bf16 k16. m1 inputs pre-scaled x16, W2 x64 at
// staging (relu commutes with positive scale); epilogue un-scales via fmaf(C1,
// 1/1024, b2). sB for all 16 j staged in prologue: NO syncs in the subtile loop.
#define SCL_IN   16.0f
#define SCL_W2   64.0f
#define INV_SCL  0.0009765625f   // 1/1024
__global__ void __launch_bounds__(256) pair_mma_kernel(
    const float* __restrict__ J, const float* __restrict__ mp_W1,
    const float* __restrict__ W2, const float* __restrict__ b2,
    const float* __restrict__ W3, const float* __restrict__ b3)
{
    __shared__ unsigned char sW2f8[HM * 72];        // e4m3 [n][k], 72B rows (conflict-free)
    __shared__ __nv_bfloat16 sW3[SD * 72];          // bf16 [c][k2], padded rows
    __shared__ alignas(16) float sA[TI * 72];       // 16*A, i-local x 64, stride 72
    __shared__ alignas(16) float sB[16 * HM];       // 16*B, ALL 16 j rows
    __shared__ alignas(16) float swJ[HM];           // 16*wJ
    __shared__ float sb2[HM], sb3[SD];

    const int t = threadIdx.x, w = t >> 5, l = t & 31;
    const int jbase = blockIdx.x * (TJS * NSUB), i0 = blockIdx.y * TI;

    for (int idx = t; idx < HM * 32; idx += 256) {          // W2 -> e4m3 x64
        const int n = idx >> 5, kp = idx & 31;
        float2 v = *reinterpret_cast<const float2*>(&W2[n * 64 + 2 * kp]);
        __nv_fp8x2_storage_t p = __nv_cvt_float2_to_fp8x2(
            make_float2(v.x * SCL_W2, v.y * SCL_W2), __NV_SATFINITE, __NV_E4M3);
        *reinterpret_cast<unsigned short*>(sW2f8 + n * 72 + 2 * kp) = p;
    }
    for (int idx = t; idx < SD * HM; idx += 256)
        sW3[(idx >> 6) * 72 + (idx & 63)] = __float2bfloat16(W3[idx]);
    for (int idx = t; idx < TI * HM; idx += 256)
        sA[(idx >> 6) * 72 + (idx & 63)] = SCL_IN * g_A[(i0 + (idx >> 6)) * HM + (idx & 63)];
    for (int idx = t; idx < 16 * HM; idx += 256)
        sB[idx] = SCL_IN * g_B[(jbase + (idx >> 6)) * HM + (idx & 63)];
    if (t < HM) { swJ[t] = SCL_IN * mp_W1[t * 67 + 64]; sb2[t] = b2[t]; }
    if (t < SD) sb3[t] = b3[t];
    __syncthreads();

    const int jl = w >> 1;            // warp's j (local within subtile)
    const int g = l >> 2, q = l & 3;  // groupID, threadID-in-group
    const int ilo = (w & 1) * 16 + g;
    const int ihi = ilo + 8;
    const float4* wj4 = reinterpret_cast<const float4*>(swJ);
    const float4* sa4 = reinterpret_cast<const float4*>(sA);

    for (int sub = 0; sub < NSUB; sub++) {
        const int j0 = jbase + sub * TJS;
        const int jrow = sub * TJS + jl;
        const float4* sb4 = reinterpret_cast<const float4*>(sB) + jrow * 16;

        const float Jlo = J[(i0 + ilo) * NND + (j0 + jl)];
        const float Jhi = J[(i0 + ihi) * NND + (j0 + jl)];

        float C1[8][4];
#pragma unroll
        for (int nt = 0; nt < 8; nt++)
#pragma unroll
            for (int r = 0; r < 4; r++) C1[nt][r] = 0.f;

        // ---------------- stage 1 (fp8): m2 accum = (16*m1) @ (64*W2)^T
#pragma unroll
        for (int c = 0; c < 2; c++) {
            const int f4 = 8 * c + q;
            const float4 wja = wj4[f4],            wjb = wj4[f4 + 4];
            const float4 ala = sa4[ilo * 18 + f4], alb = sa4[ilo * 18 + f4 + 4];
            const float4 aha = sa4[ihi * 18 + f4], ahb = sa4[ihi * 18 + f4 + 4];
            const float4 bba = sb4[f4],            bbb = sb4[f4 + 4];

            const unsigned a0 = packf8x4(
                frelu(fmaf(Jlo, wja.x, ala.x + bba.x)),
                frelu(fmaf(Jlo, wja.y, ala.y + bba.y)),
                frelu(fmaf(Jlo, wja.z, ala.z + bba.z)),
                frelu(fmaf(Jlo, wja.w, ala.w + bba.w)));
            const unsigned a1 = packf8x4(
                frelu(fmaf(Jhi, wja.x, aha.x + bba.x)),
                frelu(fmaf(Jhi, wja.y, aha.y + bba.y)),
                frelu(fmaf(Jhi, wja.z, aha.z + bba.z)),
                frelu(fmaf(Jhi, wja.w, aha.w + bba.w)));
            const unsigned a2 = packf8x4(
                frelu(fmaf(Jlo, wjb.x, alb.x + bbb.x)),
                frelu(fmaf(Jlo, wjb.y, alb.y + bbb.y)),
                frelu(fmaf(Jlo, wjb.z, alb.z + bbb.z)),
                frelu(fmaf(Jlo, wjb.w, alb.w + bbb.w)));
            const unsigned a3 = packf8x4(
                frelu(fmaf(Jhi, wjb.x, ahb.x + bbb.x)),
                frelu(fmaf(Jhi, wjb.y, ahb.y + bbb.y)),
                frelu(fmaf(Jhi, wjb.z, ahb.z + bbb.z)),
                frelu(fmaf(Jhi, wjb.w, ahb.w + bbb.w)));

#pragma unroll
            for (int nt = 0; nt < 8; nt++) {
                const int n = nt * 8 + g;
                const unsigned b0 = *reinterpret_cast<const unsigned*>(sW2f8 + n * 72 + 32 * c + 4 * q);
                const unsigned b1 = *reinterpret_cast<const unsigned*>(sW2f8 + n * 72 + 32 * c + 16 + 4 * q);
                mma16832(C1[nt], a0, a1, a2, a3, b0, b1);
            }
        }

        // ---------------- un-scale + bias + relu + repack -> stage-2 bf16 A fragments
        unsigned A2[4][4];
#pragma unroll
        for (int nt = 0; nt < 8; nt++) {
            const float2 bias = *reinterpret_cast<const float2*>(&sb2[nt * 8 + 2 * q]);
            const float e0 = frelu(fmaf(C1[nt][0], INV_SCL, bias.x));
            const float e1 = frelu(fmaf(C1[nt][1], INV_SCL, bias.y));
            const float e2 = frelu(fmaf(C1[nt][2], INV_SCL, bias.x));
            const float e3 = frelu(fmaf(C1[nt][3], INV_SCL, bias.y));
            const int kt2 = nt >> 1;
            if ((nt & 1) == 0) { A2[kt2][0] = packbf(e0, e1); A2[kt2][1] = packbf(e2, e3); }
            else               { A2[kt2][2] = packbf(e0, e1); A2[kt2][3] = packbf(e2, e3); }
        }

        // ---------------- stage 2 (bf16): msg = m2 @ W3^T
        float C2[4][4];
#pragma unroll
        for (int nt = 0; nt < 4; nt++)
#pragma unroll
            for (int r = 0; r < 4; r++) C2[nt][r] = 0.f;

#pragma unroll
        for (int kt = 0; kt < 4; kt++) {
#pragma unroll
            for (int nt = 0; nt < 4; nt++) {
                const int n = nt * 8 + g;
                const unsigned b0 = *reinterpret_cast<const unsigned*>(&sW3[n * 72 + kt * 16 + 2 * q]);
                const unsigned b1 = *reinterpret_cast<const unsigned*>(&sW3[n * 72 + kt * 16 + 2 * q + 8]);
                mma16816(C2[nt], A2[kt][0], A2[kt][1], A2[kt][2], A2[kt][3], b0, b1);
            }
        }

        // ---------------- epilogue: relu(+b3), reduce over warp's 16 i-rows
#pragma unroll
        for (int nt = 0; nt < 4; nt++) {
            const float2 bias = *reinterpret_cast<const float2*>(&sb3[nt * 8 + 2 * q]);
            float s0 = frelu(C2[nt][0] + bias.x) + frelu(C2[nt][2] + bias.x);
            float s1 = frelu(C2[nt][1] + bias.y) + frelu(C2[nt][3] + bias.y);
#pragma unroll
            for (int m = 4; m < 32; m <<= 1) {
                s0 += __shfl_xor_sync(0xffffffffu, s0, m);
                s1 += __shfl_xor_sync(0xffffffffu, s1, m);
            }
            if (g == 0) {
                atomicAdd(&g_msg[(j0 + jl) * SD + nt * 8 + 2 * q],     s0);
                atomicAdd(&g_msg[(j0 + jl) * SD + nt * 8 + 2 * q + 1], s1);
            }
        }
    }
}

// ----------------------------------------------------------------- GRU step (R8-proven)
__global__ void __launch_bounds__(256) gru_kernel(
    const float* __restrict__ hin, float* __restrict__ hout,
    const float* __restrict__ Wih, const float* __restrict__ Whh,
    const float* __restrict__ bih, const float* __restrict__ bhh)
{
    __shared__ float sh[32 * 33], sm[32 * 33];
    const int t = threadIdx.x, w = t >> 5, lane = t & 31;
    const int n0 = blockIdx.x * 32;
    const int d = blockIdx.y * 8 + w;
    for (int idx = t; idx < 1024; idx += 256) {
        int r = idx >> 5, c = idx & 31;
        sh[r * 33 + c] = hin[(n0 + r) * SD + c];
        sm[r * 33 + c] = g_msg[(n0 + r) * SD + c];
    }
    __syncthreads();
    const float* Wr = Wih + d * 64;
    const float* Wz = Wih + (32 + d) * 64;
    const float* Wn = Wih + (64 + d) * 64;
    const float* Vr = Whh + d * 32;
    const float* Vz = Whh + (32 + d) * 32;
    const float* Vn = Whh + (64 + d) * 32;
    float ir = bih[d], iz = bih[32 + d], inn = bih[64 + d];
    float hr = bhh[d], hz = bhh[32 + d], hn = bhh[64 + d];
#pragma unroll 8
    for (int c = 0; c < 32; c++) {
        float hv = sh[lane * 33 + c], mv = sm[lane * 33 + c];
        ir  += Wr[c] * hv; ir  += Wr[32 + c] * mv;
        iz  += Wz[c] * hv; iz  += Wz[32 + c] * mv;
        inn += Wn[c] * hv; inn += Wn[32 + c] * mv;
        hr += Vr[c] * hv; hz += Vz[c] * hv; hn += Vn[c] * hv;
    }
    float r = 1.f / (1.f + expf(-(ir + hr)));
    float z = 1.f / (1.f + expf(-(iz + hz)));
    float n = tanhf(inn + r * hn);
    hout[(n0 + lane) * SD + d] = (1.f - z) * n + z * sh[lane * 33 + d];
}

// ----------------------------------------------------------------- readout
__global__ void __launch_bounds__(256) readout_kernel(
    const float* __restrict__ h,
    const float* __restrict__ W1, const float* __restrict__ b1,
    const float* __restrict__ W2, const float* __restrict__ b2,
    const float* __restrict__ W3, const float* __restrict__ b3,
    float* __restrict__ out)
{
    __shared__ float sh[32 * 33];
    __shared__ float sy1[64 * 33];
    __shared__ float sy2[64 * 33];
    const int t = threadIdx.x, w = t >> 5, lane = t & 31;
    const int n0 = blockIdx.x * 32;
    for (int idx = t; idx < 1024; idx += 256) {
        int r = idx >> 5, c = idx & 31;
        sh[r * 33 + c] = h[(n0 + r) * SD + c];
    }
    __syncthreads();
    for (int k = w; k < 64; k += 8) {
        float acc = b1[k];
        const float* Wrow = W1 + k * 32;
#pragma unroll
        for (int c = 0; c < 32; c++) acc += Wrow[c] * sh[lane * 33 + c];
        sy1[k * 33 + lane] = fmaxf(acc, 0.f);
    }
    __syncthreads();
    for (int k = w; k < 64; k += 8) {
        float acc = b2[k];
        const float* Wrow = W2 + k * 64;
#pragma unroll
        for (int c = 0; c < 64; c++) acc += Wrow[c] * sy1[c * 33 + lane];
        sy2[k * 33 + lane] = fmaxf(acc, 0.f);
    }
    __syncthreads();
    if (w < 2) {
        float acc = b3[w];
        const float* Wrow = W3 + w * 64;
#pragma unroll
        for (int c = 0; c < 64; c++) acc += Wrow[c] * sy2[c * 33 + lane];
        float y = fmaxf(acc, 0.f);
        out[(n0 + lane) * 2 + w] = 1.f / (1.f + expf(-y));
    }
}

extern "C" void kernel_launch(void* const* d_in, const int* in_sizes, int n_in,
                              void* d_out, int out_size)
{
    const float* J      = (const float*)d_in[0];
    const float* b      = (const float*)d_in[1];
    const float* mp_W1  = (const float*)d_in[2];
    const float* mp_b1  = (const float*)d_in[3];
    const float* mp_W2  = (const float*)d_in[4];
    const float* mp_b2  = (const float*)d_in[5];
    const float* mp_W3  = (const float*)d_in[6];
    const float* mp_b3  = (const float*)d_in[7];
    const float* Wih    = (const float*)d_in[8];
    const float* Whh    = (const float*)d_in[9];
    const float* bih    = (const float*)d_in[10];
    const float* bhh    = (const float*)d_in[11];
    const float* rW1    = (const float*)d_in[12];
    const float* rb1    = (const float*)d_in[13];
    const float* rW2    = (const float*)d_in[14];
    const float* rb2    = (const float*)d_in[15];
    const float* rW3    = (const float*)d_in[16];
    const float* rb3    = (const float*)d_in[17];
    float* out = (float*)d_out;

    float *p_h0 = nullptr, *p_h1 = nullptr;
    cudaGetSymbolAddress((void**)&p_h0, g_h0);
    cudaGetSymbolAddress((void**)&p_h1, g_h1);

    // step-0 closed-form prep (h = 0): A/B + h/msg zero + W1T build
    prep0_kernel<<<128, 256>>>(b, mp_W1, mp_b1);

    float* hcur = p_h0;
    float* hnext = p_h1;
    dim3 g2(NND / (TJS * NSUB), NND / TI);   // (32, 16) blocks, 4 subtiles each
    for (int s = 0; s < 5; s++) {
        pair_mma_kernel<<<g2, 256>>>(J, mp_W1, mp_W2, mp_b2, mp_W3, mp_b3);
        gru_kernel<<<dim3(16, 4), 256>>>(hcur, hnext, Wih, Whh, bih, bhh);
        if (s < 4)
            prep_kernel<<<128, 256>>>(hnext, b, mp_b1);
        float* tmp = hcur; hcur = hnext; hnext = tmp;
    }
    readout_kernel<<<16, 256>>>(hcur, rW1, rb1, rW2, rb2, rW3, rb3, out);
}